// round 8
// baseline (speedup 1.0000x reference)
#include <cuda_runtime.h>
#include <cstdint>

// B=32, S=2048, F=512. Output == per-row one-hot of argmax(logits+gumbel):
// the straight-through mask is exactly one-hot in fp32, and the reference's
// top-K(=104857) "zero the smallest" scatter only touches entries that are
// already exactly zero (1,046,528 exact zeros per batch >> K). So the whole
// problem reduces to a per-row argmax + one-hot write: a pure 384 MiB stream.
//
// CONVERGED (R7): pinned at the mixed-R/W HBM ceiling (6.6 TB/s, 83% DRAM
// active), all compute pipes <18%. Measured bracketing:
//   - MLP_p1=8 @ 512-thread blocks: 52.96-53.28us  (this kernel)
//   - MLP_p1=16 (2 rows/warp): 61.8us (L1tex-queue contention + occ drop)
//   - .cs streaming hints: 55.3us (regression)
//   - split memset + read/scatter kernels: modeled >=56us (rejected)

static constexpr int F_DIM   = 512;
static constexpr int F4      = F_DIM / 4;        // 128 float4 per row
static constexpr int ROWS    = 32 * 2048;        // 65536
static constexpr int WARPS_B = 16;               // warps (rows) per block
static constexpr int THREADS = WARPS_B * 32;     // 512

__global__ __launch_bounds__(THREADS)
void onehot_argmax_kernel(const float4* __restrict__ logits,
                          const float4* __restrict__ gumbel,
                          float4* __restrict__ out) {
    const int warp = blockIdx.x * WARPS_B + (threadIdx.x >> 5);
    const int lane = threadIdx.x & 31;
    const size_t base = (size_t)warp * F4;

    float s[16];

    // Front-batched, fully coalesced loads (8 LDG.128 per lane, MLP_p1=8).
    #pragma unroll
    for (int it = 0; it < 4; it++) {
        const int off = it * 32 + lane;
        const float4 a = logits[base + off];
        const float4 g = gumbel[base + off];
        s[it * 4 + 0] = a.x + g.x;
        s[it * 4 + 1] = a.y + g.y;
        s[it * 4 + 2] = a.z + g.z;
        s[it * 4 + 3] = a.w + g.w;
    }

    // Value max: 15 fmaxf (fma pipe) + 5-step butterfly.
    float vmax = s[0];
    #pragma unroll
    for (int i = 1; i < 16; i++) vmax = fmaxf(vmax, s[i]);
    #pragma unroll
    for (int o = 16; o > 0; o >>= 1)
        vmax = fmaxf(vmax, __shfl_xor_sync(0xFFFFFFFFu, vmax, o));

    // Index of FIRST occurrence of vmax (jnp argmax tie-break):
    // per-lane min matching index, then one REDUX.min across the warp.
    unsigned cand = 0xFFFFFFFFu;
    #pragma unroll
    for (int it = 0; it < 4; it++) {
        const int e = (it * 32 + lane) * 4;
        #pragma unroll
        for (int c = 0; c < 4; c++) {
            if (s[it * 4 + c] == vmax) cand = min(cand, (unsigned)(e + c));
        }
    }
    const unsigned best = __reduce_min_sync(0xFFFFFFFFu, cand);

    // Coalesced one-hot stores (4 STG.128 per lane).
    #pragma unroll
    for (int it = 0; it < 4; it++) {
        const int off = it * 32 + lane;
        const unsigned e = (unsigned)(off * 4);
        float4 v = make_float4(0.f, 0.f, 0.f, 0.f);
        const unsigned d = best - e;
        if (d < 4u) (&v.x)[d] = 1.0f;
        out[base + off] = v;
    }
}

extern "C" void kernel_launch(void* const* d_in, const int* in_sizes, int n_in,
                              void* d_out, int out_size) {
    const float4* logits = (const float4*)d_in[0];
    const float4* gumbel = (const float4*)d_in[1];
    float4* out = (float4*)d_out;

    onehot_argmax_kernel<<<ROWS / WARPS_B, THREADS>>>(logits, gumbel, out);
}

// round 10
// speedup vs baseline: 1.0107x; 1.0107x over previous
#include <cuda_runtime.h>
#include <cstdint>

// B=32, S=2048, F=512. Output == per-row one-hot of argmax(logits+gumbel):
// the straight-through mask is exactly one-hot in fp32, and the reference's
// top-K(=104857) "zero the smallest" scatter only touches entries that are
// already exactly zero (1,046,528 exact zeros per batch >> K). So the whole
// problem reduces to a per-row argmax + one-hot write: a pure 384 MiB stream.
//
// R8: converged R7 kernel (53.0us, 83.5% DRAM, 3x reproduced) + one
// controlled change: __ldcg on the touch-once input loads (L1-bypass,
// default L2 policy — unlike R2's .cs which changed L2 evict priority and
// regressed). Stores stay default. Prediction: neutral to -0.5us.

static constexpr int F_DIM   = 512;
static constexpr int F4      = F_DIM / 4;        // 128 float4 per row
static constexpr int ROWS    = 32 * 2048;        // 65536
static constexpr int WARPS_B = 16;               // warps (rows) per block
static constexpr int THREADS = WARPS_B * 32;     // 512

__global__ __launch_bounds__(THREADS)
void onehot_argmax_kernel(const float4* __restrict__ logits,
                          const float4* __restrict__ gumbel,
                          float4* __restrict__ out) {
    const int warp = blockIdx.x * WARPS_B + (threadIdx.x >> 5);
    const int lane = threadIdx.x & 31;
    const size_t base = (size_t)warp * F4;

    float s[16];

    // Front-batched, fully coalesced loads (8 LDG.E.128.CG per lane,
    // MLP_p1=8). .cg: no L1 allocation for touch-once data.
    #pragma unroll
    for (int it = 0; it < 4; it++) {
        const int off = it * 32 + lane;
        const float4 a = __ldcg(&logits[base + off]);
        const float4 g = __ldcg(&gumbel[base + off]);
        s[it * 4 + 0] = a.x + g.x;
        s[it * 4 + 1] = a.y + g.y;
        s[it * 4 + 2] = a.z + g.z;
        s[it * 4 + 3] = a.w + g.w;
    }

    // Value max: 15 fmaxf (fma pipe) + 5-step butterfly.
    float vmax = s[0];
    #pragma unroll
    for (int i = 1; i < 16; i++) vmax = fmaxf(vmax, s[i]);
    #pragma unroll
    for (int o = 16; o > 0; o >>= 1)
        vmax = fmaxf(vmax, __shfl_xor_sync(0xFFFFFFFFu, vmax, o));

    // Index of FIRST occurrence of vmax (jnp argmax tie-break):
    // per-lane min matching index, then one REDUX.min across the warp.
    unsigned cand = 0xFFFFFFFFu;
    #pragma unroll
    for (int it = 0; it < 4; it++) {
        const int e = (it * 32 + lane) * 4;
        #pragma unroll
        for (int c = 0; c < 4; c++) {
            if (s[it * 4 + c] == vmax) cand = min(cand, (unsigned)(e + c));
        }
    }
    const unsigned best = __reduce_min_sync(0xFFFFFFFFu, cand);

    // Coalesced one-hot stores (4 STG.128 per lane), default policy.
    #pragma unroll
    for (int it = 0; it < 4; it++) {
        const int off = it * 32 + lane;
        const unsigned e = (unsigned)(off * 4);
        float4 v = make_float4(0.f, 0.f, 0.f, 0.f);
        const unsigned d = best - e;
        if (d < 4u) (&v.x)[d] = 1.0f;
        out[base + off] = v;
    }
}

extern "C" void kernel_launch(void* const* d_in, const int* in_sizes, int n_in,
                              void* d_out, int out_size) {
    const float4* logits = (const float4*)d_in[0];
    const float4* gumbel = (const float4*)d_in[1];
    float4* out = (float4*)d_out;

    onehot_argmax_kernel<<<ROWS / WARPS_B, THREADS>>>(logits, gumbel, out);
}

// round 12
// speedup vs baseline: 1.0207x; 1.0098x over previous
#include <cuda_runtime.h>
#include <cstdint>

// B=32, S=2048, F=512. Output == per-row one-hot of argmax(logits+gumbel):
// the straight-through mask is exactly one-hot in fp32, and the reference's
// top-K(=104857) "zero the smallest" scatter only touches entries that are
// already exactly zero (1,046,528 exact zeros per batch >> K). So the whole
// problem reduces to a per-row argmax + one-hot write: a pure 384 MiB stream.
//
// FINAL (R11 == R10 resubmit; R10 bench died to container infra, never ran).
// Pinned at the mixed-R/W HBM ceiling (6.6 TB/s, ~83.5% DRAM active),
// compute pipes <18%. Exhaustive bracketing on record:
//   - default cache, MLP_p1=8, 512-thr blocks: 52.96/53.06/53.28us  <= this
//   - __ldcg loads:            53.60us (neutral; L1 is pass-through anyway)
//   - .cs loads+stores:        55.3us  (L2 evict-first regression)
//   - 2 rows/warp (MLP_p1=16): 61.8us  (L1tex-queue contention, occ 42%)
//   - split memset+scatter:    modeled >=56us (rejected)

static constexpr int F_DIM   = 512;
static constexpr int F4      = F_DIM / 4;        // 128 float4 per row
static constexpr int ROWS    = 32 * 2048;        // 65536
static constexpr int WARPS_B = 16;               // warps (rows) per block
static constexpr int THREADS = WARPS_B * 32;     // 512

__global__ __launch_bounds__(THREADS)
void onehot_argmax_kernel(const float4* __restrict__ logits,
                          const float4* __restrict__ gumbel,
                          float4* __restrict__ out) {
    const int warp = blockIdx.x * WARPS_B + (threadIdx.x >> 5);
    const int lane = threadIdx.x & 31;
    const size_t base = (size_t)warp * F4;

    float s[16];

    // Front-batched, fully coalesced loads (8 LDG.128 per lane, MLP_p1=8).
    #pragma unroll
    for (int it = 0; it < 4; it++) {
        const int off = it * 32 + lane;
        const float4 a = logits[base + off];
        const float4 g = gumbel[base + off];
        s[it * 4 + 0] = a.x + g.x;
        s[it * 4 + 1] = a.y + g.y;
        s[it * 4 + 2] = a.z + g.z;
        s[it * 4 + 3] = a.w + g.w;
    }

    // Value max: 15 fmaxf (fma pipe) + 5-step butterfly.
    float vmax = s[0];
    #pragma unroll
    for (int i = 1; i < 16; i++) vmax = fmaxf(vmax, s[i]);
    #pragma unroll
    for (int o = 16; o > 0; o >>= 1)
        vmax = fmaxf(vmax, __shfl_xor_sync(0xFFFFFFFFu, vmax, o));

    // Index of FIRST occurrence of vmax (jnp argmax tie-break):
    // per-lane min matching index, then one REDUX.min across the warp.
    unsigned cand = 0xFFFFFFFFu;
    #pragma unroll
    for (int it = 0; it < 4; it++) {
        const int e = (it * 32 + lane) * 4;
        #pragma unroll
        for (int c = 0; c < 4; c++) {
            if (s[it * 4 + c] == vmax) cand = min(cand, (unsigned)(e + c));
        }
    }
    const unsigned best = __reduce_min_sync(0xFFFFFFFFu, cand);

    // Coalesced one-hot stores (4 STG.128 per lane).
    #pragma unroll
    for (int it = 0; it < 4; it++) {
        const int off = it * 32 + lane;
        const unsigned e = (unsigned)(off * 4);
        float4 v = make_float4(0.f, 0.f, 0.f, 0.f);
        const unsigned d = best - e;
        if (d < 4u) (&v.x)[d] = 1.0f;
        out[base + off] = v;
    }
}

extern "C" void kernel_launch(void* const* d_in, const int* in_sizes, int n_in,
                              void* d_out, int out_size) {
    const float4* logits = (const float4*)d_in[0];
    const float4* gumbel = (const float4*)d_in[1];
    float4* out = (float4*)d_out;

    onehot_argmax_kernel<<<ROWS / WARPS_B, THREADS>>>(logits, gumbel, out);
}